// round 6
// baseline (speedup 1.0000x reference)
#include <cuda_runtime.h>
#include <cuda_bf16.h>

#define NB 64      // batch
#define NL 512     // sequence length
#define ND 300     // embed dim
#define ND4 75     // float4 lanes per row
#define NC 128     // channels
#define CH 16      // token chunks per batch
#define TPC 32     // tokens per gather block (NL/CH)
#define WAYS 4
#define JPER 8     // tokens per way (TPC/WAYS)

// Scratch (__device__ globals per allocation rules)
__device__ float4 g_part4[NB * CH * 3 * ND4];  // partial g sums, f4
__device__ float4 g_h4[NB * 96];               // h[b][384] as f4

// ---------------------------------------------------------------------------
// Kernel 1: embedding gather + weighted partial reduction.
// grid = NB*CH = 1024 blocks, 320 threads = 80 f4 d-lanes x 4 token-ways.
// 6 blocks/SM resident -> ~60 warps/SM to cover DRAM latency.
// ---------------------------------------------------------------------------
__global__ __launch_bounds__(320, 6) void gather_kernel(
    const int*   __restrict__ x,
    const float* __restrict__ embed_w,
    const float* __restrict__ fc3_w,
    const float* __restrict__ fc4_w,
    const float* __restrict__ fc5_w)
{
    const int b     = blockIdx.x >> 4;
    const int chunk = blockIdx.x & 15;

    __shared__ int    sidx[TPC];
    __shared__ float  sc[3][TPC];
    __shared__ float4 sred[WAYS][3][80];

    const int tid = threadIdx.x;
    const int d4  = tid % 80;
    const int y   = tid / 80;

    if (tid < TPC) {
        const int t = chunk * TPC + tid;
        sidx[tid] = x[b * NL + t];
        const float* wks[3] = {fc3_w, fc4_w, fc5_w};
        #pragma unroll
        for (int kk = 0; kk < 3; kk++) {
            const int k = kk + 3;
            int lo = t - k + 1; if (lo < 0) lo = 0;
            int hi = t; const int lim = NL - k - 1; if (hi > lim) hi = lim;
            float s = 0.f;
            for (int l = lo; l <= hi; l++) s += wks[kk][l];
            sc[kk][tid] = s;
        }
    }
    __syncthreads();

    float4 a0 = make_float4(0.f, 0.f, 0.f, 0.f);
    float4 a1 = a0, a2 = a0;

    if (d4 < ND4) {
        const float4* emb4 = (const float4*)embed_w;
        #pragma unroll 4
        for (int j = 0; j < JPER; j++) {
            const int jj = y * JPER + j;
            const float4 v = __ldg(&emb4[sidx[jj] * ND4 + d4]);
            const float c0 = sc[0][jj], c1 = sc[1][jj], c2 = sc[2][jj];
            a0.x = fmaf(c0, v.x, a0.x); a0.y = fmaf(c0, v.y, a0.y);
            a0.z = fmaf(c0, v.z, a0.z); a0.w = fmaf(c0, v.w, a0.w);
            a1.x = fmaf(c1, v.x, a1.x); a1.y = fmaf(c1, v.y, a1.y);
            a1.z = fmaf(c1, v.z, a1.z); a1.w = fmaf(c1, v.w, a1.w);
            a2.x = fmaf(c2, v.x, a2.x); a2.y = fmaf(c2, v.y, a2.y);
            a2.z = fmaf(c2, v.z, a2.z); a2.w = fmaf(c2, v.w, a2.w);
        }
    }
    sred[y][0][d4] = a0;
    sred[y][1][d4] = a1;
    sred[y][2][d4] = a2;
    __syncthreads();

    if (tid < 240) {
        const int kk = tid / 80;
        const int dd = tid % 80;
        if (dd < ND4) {
            float4 s = sred[0][kk][dd];
            #pragma unroll
            for (int w = 1; w < WAYS; w++) {
                const float4 v = sred[w][kk][dd];
                s.x += v.x; s.y += v.y; s.z += v.z; s.w += v.w;
            }
            g_part4[((b * CH + chunk) * 3 + kk) * ND4 + dd] = s;
        }
    }
}

// ---------------------------------------------------------------------------
// Kernel 2: sim = conv(g) + conv_b*S_k + b_k  -> g_h.
// grid (4 ctiles, 16 btiles) = 64 blocks, 128 threads = 32 ch x 4 batches.
// Per-thread private dot products (no shuffles). conv_w tile in smem.
// Dynamic smem: cw[2400 f4] + sg[900 f4] = 52800 B.
// ---------------------------------------------------------------------------
__global__ __launch_bounds__(128) void sim_kernel(
    const float* __restrict__ conv_w,
    const float* __restrict__ conv_b,
    const float* __restrict__ fc3_w,
    const float* __restrict__ fc3_b,
    const float* __restrict__ fc4_w,
    const float* __restrict__ fc4_b,
    const float* __restrict__ fc5_w,
    const float* __restrict__ fc5_b)
{
    extern __shared__ float4 dyn[];
    float4* cw_s = dyn;            // [32][75]
    float4* sg   = dyn + 2400;     // [4][3*75]
    __shared__ float sSk[3];

    const int tid  = threadIdx.x;
    const int warp = tid >> 5;
    const int lane = tid & 31;
    const int c0 = blockIdx.x * 32;
    const int b0 = blockIdx.y * 4;

    // S_k (warps 0-2; tiny)
    if (warp < 3) {
        const float* wks[3] = {fc3_w, fc4_w, fc5_w};
        const float* w = wks[warp];
        const int n = NL - (warp + 3);
        float s = 0.f;
        for (int l = lane; l < n; l += 32) s += w[l];
        #pragma unroll
        for (int off = 16; off > 0; off >>= 1)
            s += __shfl_xor_sync(0xFFFFFFFFu, s, off);
        if (lane == 0) sSk[warp] = s;
    }

    // Stage conv_w tile (rows c0..c0+31), fully coalesced
    {
        const float4* cwg = (const float4*)conv_w;
        #pragma unroll
        for (int j = tid; j < 32 * ND4; j += 128)
            cw_s[j] = __ldg(&cwg[c0 * ND4 + j]);
    }

    // Reduce g_part chunks -> sg[bsub][225]  (CH=16 independent loads each)
    for (int pos = tid; pos < 4 * 225; pos += 128) {
        const int bsub = pos / 225;
        const int i    = pos % 225;
        const float4* p = &g_part4[(b0 + bsub) * CH * 225 + i];
        float4 s = p[0];
        #pragma unroll
        for (int ch = 1; ch < CH; ch++) {
            const float4 v = p[ch * 225];
            s.x += v.x; s.y += v.y; s.z += v.z; s.w += v.w;
        }
        sg[bsub * 225 + i] = s;
    }
    __syncthreads();

    // Private dots: thread (c=lane, bsub=warp)
    const int c    = lane;
    const int bsub = warp;
    float s0 = 0.f, s1 = 0.f, s2 = 0.f;
    #pragma unroll 5
    for (int i = 0; i < ND4; i++) {
        const float4 w  = cw_s[c * ND4 + i];           // conflict-free (stride 75 f4)
        const float4 g0 = sg[bsub * 225 + i];          // broadcast
        const float4 g1 = sg[bsub * 225 + 75 + i];
        const float4 g2 = sg[bsub * 225 + 150 + i];
        s0 = fmaf(w.x, g0.x, s0); s0 = fmaf(w.y, g0.y, s0);
        s0 = fmaf(w.z, g0.z, s0); s0 = fmaf(w.w, g0.w, s0);
        s1 = fmaf(w.x, g1.x, s1); s1 = fmaf(w.y, g1.y, s1);
        s1 = fmaf(w.z, g1.z, s1); s1 = fmaf(w.w, g1.w, s1);
        s2 = fmaf(w.x, g2.x, s2); s2 = fmaf(w.y, g2.y, s2);
        s2 = fmaf(w.z, g2.z, s2); s2 = fmaf(w.w, g2.w, s2);
    }

    const float cb = conv_b[c0 + c];
    const int b = b0 + bsub;
    float* h = (float*)g_h4;                // h[b][384]
    h[b * 384 + 0 * NC + c0 + c] = s0 + cb * sSk[0] + fc3_b[0];
    h[b * 384 + 1 * NC + c0 + c] = s1 + cb * sSk[1] + fc4_b[0];
    h[b * 384 + 2 * NC + c0 + c] = s2 + cb * sSk[2] + fc5_b[0];
}

// ---------------------------------------------------------------------------
// Kernel 3: out = h @ fc_w^T + fc_b.
// grid (4 cotiles, 16 btiles) = 64 blocks, 128 threads = 32 co x 4 batches.
// fc_w tile rows padded to 97 f4 in smem (96 would be 32-way bank conflict).
// Dynamic smem: fw[32*97 f4] + sh[384 f4] = 55808 B.
// ---------------------------------------------------------------------------
__global__ __launch_bounds__(128) void fc_kernel(
    const float* __restrict__ fc_w,
    const float* __restrict__ fc_b,
    float* __restrict__ out)
{
    extern __shared__ float4 dyn[];
    float4* fw_s = dyn;            // [32][97] (padded)
    float4* sh   = dyn + 32 * 97;  // [4][96]

    const int tid = threadIdx.x;
    const int c0 = blockIdx.x * 32;
    const int b0 = blockIdx.y * 4;

    {
        const float4* fwg = (const float4*)fc_w;
        #pragma unroll
        for (int j = tid; j < 32 * 96; j += 128) {
            const int r = j / 96, i = j % 96;
            fw_s[r * 97 + i] = __ldg(&fwg[(c0 + r) * 96 + i]);
        }
        #pragma unroll
        for (int j = tid; j < 4 * 96; j += 128)
            sh[j] = g_h4[b0 * 96 + j];
    }
    __syncthreads();

    const int co   = tid & 31;
    const int bsub = tid >> 5;
    float o = 0.f;
    #pragma unroll 8
    for (int i = 0; i < 96; i++) {
        const float4 w = fw_s[co * 97 + i];    // conflict-free (stride 97 f4)
        const float4 h = sh[bsub * 96 + i];    // broadcast
        o = fmaf(w.x, h.x, o); o = fmaf(w.y, h.y, o);
        o = fmaf(w.z, h.z, o); o = fmaf(w.w, h.w, o);
    }
    out[(b0 + bsub) * NC + c0 + co] = o + fc_b[c0 + co];
}

// ---------------------------------------------------------------------------
extern "C" void kernel_launch(void* const* d_in, const int* in_sizes, int n_in,
                              void* d_out, int out_size) {
    const int*   x       = (const int*)  d_in[0];
    const float* embed_w = (const float*)d_in[1];
    const float* conv_w  = (const float*)d_in[2];
    const float* conv_b  = (const float*)d_in[3];
    const float* fc3_w   = (const float*)d_in[4];
    const float* fc3_b   = (const float*)d_in[5];
    const float* fc4_w   = (const float*)d_in[6];
    const float* fc4_b   = (const float*)d_in[7];
    const float* fc5_w   = (const float*)d_in[8];
    const float* fc5_b   = (const float*)d_in[9];
    const float* fc_w    = (const float*)d_in[10];
    const float* fc_b    = (const float*)d_in[11];
    float* out = (float*)d_out;

    const int sim_smem = (2400 + 900) * (int)sizeof(float4);      // 52800
    const int fc_smem  = (32 * 97 + 384) * (int)sizeof(float4);   // 55808
    static int smem_set = 0;
    if (!smem_set) {
        cudaFuncSetAttribute(sim_kernel, cudaFuncAttributeMaxDynamicSharedMemorySize, sim_smem);
        cudaFuncSetAttribute(fc_kernel,  cudaFuncAttributeMaxDynamicSharedMemorySize, fc_smem);
        smem_set = 1;
    }

    gather_kernel<<<NB * CH, 320>>>(x, embed_w, fc3_w, fc4_w, fc5_w);
    sim_kernel<<<dim3(4, 16), 128, sim_smem>>>(conv_w, conv_b, fc3_w, fc3_b,
                                               fc4_w, fc4_b, fc5_w, fc5_b);
    fc_kernel<<<dim3(4, 16), 128, fc_smem>>>(fc_w, fc_b, out);
}

// round 7
// speedup vs baseline: 1.4189x; 1.4189x over previous
#include <cuda_runtime.h>
#include <cuda_bf16.h>

#define NB 64      // batch
#define NL 512     // sequence length
#define ND 300     // embed dim
#define ND4 75     // float4 lanes per row
#define NC 128     // channels
#define CH 16      // token chunks per batch
#define TPC 32     // tokens per gather block (NL/CH)
#define WAYS 4
#define JPER 8     // tokens per way (TPC/WAYS)

// Scratch (__device__ globals per allocation rules)
__device__ float4 g_part4[NB * CH * 3 * ND4];  // partial g sums
__device__ float4 g_g4[NB * 3 * ND4];          // reduced g[b][3*75]
__device__ float4 g_h4[NB * 96];               // h[b][384]

// ---------------------------------------------------------------------------
// Kernel 1: embedding gather + weighted partial reduction.
// grid = NB*CH = 1024 blocks, 320 threads = 80 f4 d-lanes x 4 token-ways.
// Prologue parallelized across 128 threads (no single-warp serialization).
// ---------------------------------------------------------------------------
__global__ __launch_bounds__(320, 6) void gather_kernel(
    const int*   __restrict__ x,
    const float* __restrict__ embed_w,
    const float* __restrict__ fc3_w,
    const float* __restrict__ fc4_w,
    const float* __restrict__ fc5_w)
{
    const int b     = blockIdx.x >> 4;
    const int chunk = blockIdx.x & 15;

    __shared__ int    sidx[TPC];
    __shared__ float  sc[3][TPC];
    __shared__ float4 sred[WAYS][3][80];

    const int tid = threadIdx.x;
    const int d4  = tid % 80;
    const int y   = tid / 80;

    // Parallel prologue: 96 threads -> one (kk, t) coef each; 32 -> indices.
    if (tid < 96) {
        const int kk = tid >> 5;          // 0..2
        const int tt = tid & 31;
        const int t  = chunk * TPC + tt;
        const float* wk = (kk == 0) ? fc3_w : (kk == 1) ? fc4_w : fc5_w;
        const int k = kk + 3;
        int lo = t - k + 1; if (lo < 0) lo = 0;
        int hi = t; const int lim = NL - k - 1; if (hi > lim) hi = lim;
        float s = 0.f;
        #pragma unroll 5
        for (int l = lo; l <= hi; l++) s += __ldg(&wk[l]);
        sc[kk][tt] = s;
    } else if (tid < 128) {
        const int tt = tid - 96;
        sidx[tt] = __ldg(&x[b * NL + chunk * TPC + tt]);
    }
    __syncthreads();

    float4 a0 = make_float4(0.f, 0.f, 0.f, 0.f);
    float4 a1 = a0, a2 = a0;

    if (d4 < ND4) {
        const float4* emb4 = (const float4*)embed_w;
        // Pre-read indices into registers, then batch the 8 LDG.128s.
        int  rix[JPER];
        #pragma unroll
        for (int j = 0; j < JPER; j++) rix[j] = sidx[y * JPER + j];
        float4 v[JPER];
        #pragma unroll
        for (int j = 0; j < JPER; j++) v[j] = __ldg(&emb4[rix[j] * ND4 + d4]);
        #pragma unroll
        for (int j = 0; j < JPER; j++) {
            const int jj = y * JPER + j;
            const float c0 = sc[0][jj], c1 = sc[1][jj], c2 = sc[2][jj];
            a0.x = fmaf(c0, v[j].x, a0.x); a0.y = fmaf(c0, v[j].y, a0.y);
            a0.z = fmaf(c0, v[j].z, a0.z); a0.w = fmaf(c0, v[j].w, a0.w);
            a1.x = fmaf(c1, v[j].x, a1.x); a1.y = fmaf(c1, v[j].y, a1.y);
            a1.z = fmaf(c1, v[j].z, a1.z); a1.w = fmaf(c1, v[j].w, a1.w);
            a2.x = fmaf(c2, v[j].x, a2.x); a2.y = fmaf(c2, v[j].y, a2.y);
            a2.z = fmaf(c2, v[j].z, a2.z); a2.w = fmaf(c2, v[j].w, a2.w);
        }
    }
    sred[y][0][d4] = a0;
    sred[y][1][d4] = a1;
    sred[y][2][d4] = a2;
    __syncthreads();

    if (tid < 240) {
        const int kk = tid / 80;
        const int dd = tid % 80;
        if (dd < ND4) {
            float4 s = sred[0][kk][dd];
            #pragma unroll
            for (int w = 1; w < WAYS; w++) {
                const float4 v = sred[w][kk][dd];
                s.x += v.x; s.y += v.y; s.z += v.z; s.w += v.w;
            }
            g_part4[((b * CH + chunk) * 3 + kk) * ND4 + dd] = s;
        }
    }
}

// ---------------------------------------------------------------------------
// Kernel 1.5: reduce the CH chunk partials once: g_part4 -> g_g4.
// grid = NB blocks, 256 threads (225 active); 16 independent LDG.128/thread.
// ---------------------------------------------------------------------------
__global__ __launch_bounds__(256) void reduce_kernel()
{
    const int b = blockIdx.x;
    const int i = threadIdx.x;
    if (i < 225) {
        const float4* p = &g_part4[b * (CH * 225) + i];
        float4 s = p[0];
        #pragma unroll
        for (int ch = 1; ch < CH; ch++) {
            const float4 v = p[ch * 225];
            s.x += v.x; s.y += v.y; s.z += v.z; s.w += v.w;
        }
        g_g4[b * 225 + i] = s;
    }
}

// ---------------------------------------------------------------------------
// Kernel 2: sim = conv(g) + conv_b*S_k + b_k  -> g_h.
// grid (4 ctiles, 16 btiles) = 64 blocks, 128 threads = 32 ch x 4 batches.
// Dynamic smem: cw[2400 f4] + sg[900 f4] = 52800 B.
// ---------------------------------------------------------------------------
__global__ __launch_bounds__(128) void sim_kernel(
    const float* __restrict__ conv_w,
    const float* __restrict__ conv_b,
    const float* __restrict__ fc3_w,
    const float* __restrict__ fc3_b,
    const float* __restrict__ fc4_w,
    const float* __restrict__ fc4_b,
    const float* __restrict__ fc5_w,
    const float* __restrict__ fc5_b)
{
    extern __shared__ float4 dyn[];
    float4* cw_s = dyn;            // [32][75]
    float4* sg   = dyn + 2400;     // [4][3*75]
    __shared__ float sSk[3];

    const int tid  = threadIdx.x;
    const int warp = tid >> 5;
    const int lane = tid & 31;
    const int c0 = blockIdx.x * 32;
    const int b0 = blockIdx.y * 4;

    // S_k (warps 0-2; tiny)
    if (warp < 3) {
        const float* wks[3] = {fc3_w, fc4_w, fc5_w};
        const float* w = wks[warp];
        const int n = NL - (warp + 3);
        float s = 0.f;
        for (int l = lane; l < n; l += 32) s += w[l];
        #pragma unroll
        for (int off = 16; off > 0; off >>= 1)
            s += __shfl_xor_sync(0xFFFFFFFFu, s, off);
        if (lane == 0) sSk[warp] = s;
    }

    // Stage conv_w tile + reduced g, coalesced
    {
        const float4* cwg = (const float4*)conv_w;
        #pragma unroll
        for (int j = tid; j < 32 * ND4; j += 128)
            cw_s[j] = __ldg(&cwg[c0 * ND4 + j]);
        #pragma unroll
        for (int j = tid; j < 4 * 225; j += 128)
            sg[j] = g_g4[b0 * 225 + j];
    }
    __syncthreads();

    // Private dots: thread (c=lane, bsub=warp)
    const int c    = lane;
    const int bsub = warp;
    float s0 = 0.f, s1 = 0.f, s2 = 0.f;
    #pragma unroll 5
    for (int i = 0; i < ND4; i++) {
        const float4 w  = cw_s[c * ND4 + i];           // conflict-free (stride 75 f4)
        const float4 g0 = sg[bsub * 225 + i];          // broadcast
        const float4 g1 = sg[bsub * 225 + 75 + i];
        const float4 g2 = sg[bsub * 225 + 150 + i];
        s0 = fmaf(w.x, g0.x, s0); s0 = fmaf(w.y, g0.y, s0);
        s0 = fmaf(w.z, g0.z, s0); s0 = fmaf(w.w, g0.w, s0);
        s1 = fmaf(w.x, g1.x, s1); s1 = fmaf(w.y, g1.y, s1);
        s1 = fmaf(w.z, g1.z, s1); s1 = fmaf(w.w, g1.w, s1);
        s2 = fmaf(w.x, g2.x, s2); s2 = fmaf(w.y, g2.y, s2);
        s2 = fmaf(w.z, g2.z, s2); s2 = fmaf(w.w, g2.w, s2);
    }

    const float cb = conv_b[c0 + c];
    const int b = b0 + bsub;
    float* h = (float*)g_h4;                // h[b][384]
    h[b * 384 + 0 * NC + c0 + c] = s0 + cb * sSk[0] + fc3_b[0];
    h[b * 384 + 1 * NC + c0 + c] = s1 + cb * sSk[1] + fc4_b[0];
    h[b * 384 + 2 * NC + c0 + c] = s2 + cb * sSk[2] + fc5_b[0];
}

// ---------------------------------------------------------------------------
// Kernel 3: out = h @ fc_w^T + fc_b.
// grid (4 cotiles, 16 btiles) = 64 blocks, 128 threads.
// Dynamic smem: fw[32*97 f4] + sh[384 f4] = 55808 B.
// ---------------------------------------------------------------------------
__global__ __launch_bounds__(128) void fc_kernel(
    const float* __restrict__ fc_w,
    const float* __restrict__ fc_b,
    float* __restrict__ out)
{
    extern __shared__ float4 dyn[];
    float4* fw_s = dyn;            // [32][97] (padded)
    float4* sh   = dyn + 32 * 97;  // [4][96]

    const int tid = threadIdx.x;
    const int c0 = blockIdx.x * 32;
    const int b0 = blockIdx.y * 4;

    {
        const float4* fwg = (const float4*)fc_w;
        #pragma unroll
        for (int j = tid; j < 32 * 96; j += 128) {
            const int r = j / 96, i = j % 96;
            fw_s[r * 97 + i] = __ldg(&fwg[(c0 + r) * 96 + i]);
        }
        #pragma unroll
        for (int j = tid; j < 4 * 96; j += 128)
            sh[j] = g_h4[b0 * 96 + j];
    }
    __syncthreads();

    const int co   = tid & 31;
    const int bsub = tid >> 5;
    float o = 0.f;
    #pragma unroll 8
    for (int i = 0; i < 96; i++) {
        const float4 w = fw_s[co * 97 + i];    // conflict-free (stride 97 f4)
        const float4 h = sh[bsub * 96 + i];    // broadcast
        o = fmaf(w.x, h.x, o); o = fmaf(w.y, h.y, o);
        o = fmaf(w.z, h.z, o); o = fmaf(w.w, h.w, o);
    }
    out[(b0 + bsub) * NC + c0 + co] = o + fc_b[c0 + co];
}

// ---------------------------------------------------------------------------
extern "C" void kernel_launch(void* const* d_in, const int* in_sizes, int n_in,
                              void* d_out, int out_size) {
    const int*   x       = (const int*)  d_in[0];
    const float* embed_w = (const float*)d_in[1];
    const float* conv_w  = (const float*)d_in[2];
    const float* conv_b  = (const float*)d_in[3];
    const float* fc3_w   = (const float*)d_in[4];
    const float* fc3_b   = (const float*)d_in[5];
    const float* fc4_w   = (const float*)d_in[6];
    const float* fc4_b   = (const float*)d_in[7];
    const float* fc5_w   = (const float*)d_in[8];
    const float* fc5_b   = (const float*)d_in[9];
    const float* fc_w    = (const float*)d_in[10];
    const float* fc_b    = (const float*)d_in[11];
    float* out = (float*)d_out;

    const int sim_smem = (2400 + 900) * (int)sizeof(float4);      // 52800
    const int fc_smem  = (32 * 97 + 384) * (int)sizeof(float4);   // 55808
    static int smem_set = 0;
    if (!smem_set) {
        cudaFuncSetAttribute(sim_kernel, cudaFuncAttributeMaxDynamicSharedMemorySize, sim_smem);
        cudaFuncSetAttribute(fc_kernel,  cudaFuncAttributeMaxDynamicSharedMemorySize, fc_smem);
        smem_set = 1;
    }

    gather_kernel<<<NB * CH, 320>>>(x, embed_w, fc3_w, fc4_w, fc5_w);
    reduce_kernel<<<NB, 256>>>();
    sim_kernel<<<dim3(4, 16), 128, sim_smem>>>(conv_w, conv_b, fc3_w, fc3_b,
                                               fc4_w, fc4_b, fc5_w, fc5_b);
    fc_kernel<<<dim3(4, 16), 128, fc_smem>>>(fc_w, fc_b, out);
}

// round 8
// speedup vs baseline: 1.8548x; 1.3072x over previous
#include <cuda_runtime.h>
#include <cuda_bf16.h>

#define NB 64      // batch
#define NL 512     // sequence length
#define ND 300     // embed dim
#define ND4 75     // float4 lanes per row
#define NC 128     // channels
#define CH 8       // token chunks per batch
#define TPC 64     // tokens per gather block
#define WAYS 4
#define JPER 16    // tokens per way

// Scratch (__device__ globals per allocation rules)
__device__ float4 g_part4[NB * CH * 3 * ND4];  // partial g sums

// ---------------------------------------------------------------------------
// Kernel 1: embedding gather + weighted partial reduction.
// grid = NB*CH = 512 blocks, 320 threads = 80 f4 d-lanes x 4 token-ways.
// Each way handles 16 tokens in two 8-deep batched LDG.128 groups.
// ---------------------------------------------------------------------------
__global__ __launch_bounds__(320, 3) void gather_kernel(
    const int*   __restrict__ x,
    const float* __restrict__ embed_w,
    const float* __restrict__ fc3_w,
    const float* __restrict__ fc4_w,
    const float* __restrict__ fc5_w)
{
    const int b     = blockIdx.x >> 3;
    const int chunk = blockIdx.x & 7;

    __shared__ int    sidx[TPC];
    __shared__ float  sc[3][TPC];
    __shared__ float4 sred[WAYS][3][80];

    const int tid = threadIdx.x;
    const int d4  = tid % 80;
    const int y   = tid / 80;

    // Parallel prologue: 192 threads -> one (kk, t) coef each; 64 -> indices.
    if (tid < 192) {
        const int kk = tid >> 6;          // 0..2
        const int tt = tid & 63;
        const int t  = chunk * TPC + tt;
        const float* wk = (kk == 0) ? fc3_w : (kk == 1) ? fc4_w : fc5_w;
        const int k = kk + 3;
        int lo = t - k + 1; if (lo < 0) lo = 0;
        int hi = t; const int lim = NL - k - 1; if (hi > lim) hi = lim;
        float s = 0.f;
        #pragma unroll 5
        for (int l = lo; l <= hi; l++) s += __ldg(&wk[l]);
        sc[kk][tt] = s;
    } else if (tid < 256) {
        const int tt = tid - 192;
        sidx[tt] = __ldg(&x[b * NL + chunk * TPC + tt]);
    }
    __syncthreads();

    float4 a0 = make_float4(0.f, 0.f, 0.f, 0.f);
    float4 a1 = a0, a2 = a0;

    if (d4 < ND4) {
        const float4* emb4 = (const float4*)embed_w;
        #pragma unroll
        for (int bb = 0; bb < 2; bb++) {
            int    rix[8];
            float4 v[8];
            #pragma unroll
            for (int j = 0; j < 8; j++) rix[j] = sidx[y * JPER + bb * 8 + j];
            #pragma unroll
            for (int j = 0; j < 8; j++) v[j] = __ldg(&emb4[rix[j] * ND4 + d4]);
            #pragma unroll
            for (int j = 0; j < 8; j++) {
                const int jj = y * JPER + bb * 8 + j;
                const float c0 = sc[0][jj], c1 = sc[1][jj], c2 = sc[2][jj];
                a0.x = fmaf(c0, v[j].x, a0.x); a0.y = fmaf(c0, v[j].y, a0.y);
                a0.z = fmaf(c0, v[j].z, a0.z); a0.w = fmaf(c0, v[j].w, a0.w);
                a1.x = fmaf(c1, v[j].x, a1.x); a1.y = fmaf(c1, v[j].y, a1.y);
                a1.z = fmaf(c1, v[j].z, a1.z); a1.w = fmaf(c1, v[j].w, a1.w);
                a2.x = fmaf(c2, v[j].x, a2.x); a2.y = fmaf(c2, v[j].y, a2.y);
                a2.z = fmaf(c2, v[j].z, a2.z); a2.w = fmaf(c2, v[j].w, a2.w);
            }
        }
    }
    sred[y][0][d4] = a0;
    sred[y][1][d4] = a1;
    sred[y][2][d4] = a2;
    __syncthreads();

    if (tid < 240) {
        const int kk = tid / 80;
        const int dd = tid % 80;
        if (dd < ND4) {
            float4 s = sred[0][kk][dd];
            #pragma unroll
            for (int w = 1; w < WAYS; w++) {
                const float4 v = sred[w][kk][dd];
                s.x += v.x; s.y += v.y; s.z += v.z; s.w += v.w;
            }
            g_part4[((b * CH + chunk) * 3 + kk) * ND4 + dd] = s;
        }
    }
}

// ---------------------------------------------------------------------------
// Kernel 2 (fused epilogue): one block per batch, 256 threads.
// Phase A: stage conv_w (150 KB) + reduce g_part -> sg; S_k.
// Phase B: conv dots, thread = (c, d-half), conflict-free.
// Phase C: combine -> h; restage fc_w (padded stride 97).
// Phase D: fc dots, thread = (c, half); combine -> out.
// Dyn smem (f4): W[12416] + sg[225] + aux[300] = 12941 f4 = 207056 B.
// ---------------------------------------------------------------------------
#define W_F4   12416
#define SG_OFF 12416
#define AUX_OFF 12641
#define EPI_SMEM (12941 * 16)

__global__ __launch_bounds__(256, 1) void epilogue_kernel(
    const float* __restrict__ conv_w,
    const float* __restrict__ conv_b,
    const float* __restrict__ fc3_w,
    const float* __restrict__ fc3_b,
    const float* __restrict__ fc4_w,
    const float* __restrict__ fc4_b,
    const float* __restrict__ fc5_w,
    const float* __restrict__ fc5_b,
    const float* __restrict__ fc_w,
    const float* __restrict__ fc_b,
    float* __restrict__ out)
{
    extern __shared__ float4 dyn[];
    float4* W    = dyn;                 // conv_w [128][75], later fc_w [128][97]
    float4* sg   = dyn + SG_OFF;        // g[3*75]
    float*  auxf = (float*)(dyn + AUX_OFF); // partials [2][384], h at +768
    __shared__ float sSk[3];

    const int tid  = threadIdx.x;
    const int warp = tid >> 5;
    const int lane = tid & 31;
    const int b    = blockIdx.x;

    // S_k (warps 0-2)
    if (warp < 3) {
        const float* wks[3] = {fc3_w, fc4_w, fc5_w};
        const float* w = wks[warp];
        const int n = NL - (warp + 3);
        float s = 0.f;
        for (int l = lane; l < n; l += 32) s += w[l];
        #pragma unroll
        for (int off = 16; off > 0; off >>= 1)
            s += __shfl_xor_sync(0xFFFFFFFFu, s, off);
        if (lane == 0) sSk[warp] = s;
    }

    // Phase A: stage conv_w (9600 f4) + reduce g_part chunks
    {
        const float4* cwg = (const float4*)conv_w;
        #pragma unroll
        for (int j = tid; j < NC * ND4; j += 256)
            W[j] = __ldg(&cwg[j]);
    }
    if (tid < 225) {
        const float4* p = &g_part4[b * (CH * 225) + tid];
        float4 s = p[0];
        #pragma unroll
        for (int ch = 1; ch < CH; ch++) {
            const float4 v = p[ch * 225];
            s.x += v.x; s.y += v.y; s.z += v.z; s.w += v.w;
        }
        sg[tid] = s;
    }
    __syncthreads();

    // Phase B: conv dots. thread -> (c = tid&127, half = tid>>7)
    const int c    = tid & 127;
    const int half = tid >> 7;
    {
        const int i0 = half ? 38 : 0;
        const int i1 = half ? ND4 : 38;
        float s0 = 0.f, s1 = 0.f, s2 = 0.f;
        #pragma unroll 4
        for (int i = i0; i < i1; i++) {
            const float4 w  = W[c * ND4 + i];
            const float4 g0 = sg[i];
            const float4 g1 = sg[75 + i];
            const float4 g2 = sg[150 + i];
            s0 = fmaf(w.x, g0.x, s0); s0 = fmaf(w.y, g0.y, s0);
            s0 = fmaf(w.z, g0.z, s0); s0 = fmaf(w.w, g0.w, s0);
            s1 = fmaf(w.x, g1.x, s1); s1 = fmaf(w.y, g1.y, s1);
            s1 = fmaf(w.z, g1.z, s1); s1 = fmaf(w.w, g1.w, s1);
            s2 = fmaf(w.x, g2.x, s2); s2 = fmaf(w.y, g2.y, s2);
            s2 = fmaf(w.z, g2.z, s2); s2 = fmaf(w.w, g2.w, s2);
        }
        auxf[half * 384 + 0 * NC + c] = s0;
        auxf[half * 384 + 1 * NC + c] = s1;
        auxf[half * 384 + 2 * NC + c] = s2;
    }
    __syncthreads();

    // Phase C: combine halves -> h (auxf+768); restage fc_w padded stride 97
    if (tid < NC) {
        const float cb = conv_b[tid];
        const float bks[3] = {fc3_b[0], fc4_b[0], fc5_b[0]};
        #pragma unroll
        for (int kk = 0; kk < 3; kk++)
            auxf[768 + kk * NC + tid] =
                auxf[kk * NC + tid] + auxf[384 + kk * NC + tid]
                + cb * sSk[kk] + bks[kk];
    }
    {
        const float4* fwg = (const float4*)fc_w;
        #pragma unroll
        for (int j = tid; j < NC * 96; j += 256) {
            const int r = j / 96, i = j % 96;
            W[r * 97 + i] = __ldg(&fwg[j]);
        }
    }
    __syncthreads();

    // Phase D: fc dots. thread -> (c, half); 48 f4 each
    {
        const float4* h4 = (const float4*)(auxf + 768);
        float o = 0.f;
        #pragma unroll 6
        for (int i = half * 48; i < half * 48 + 48; i++) {
            const float4 w = W[c * 97 + i];   // stride 97: conflict-free
            const float4 h = h4[i];           // broadcast
            o = fmaf(w.x, h.x, o); o = fmaf(w.y, h.y, o);
            o = fmaf(w.z, h.z, o); o = fmaf(w.w, h.w, o);
        }
        auxf[half * NC + c] = o;   // conv partials already consumed
    }
    __syncthreads();

    if (tid < NC)
        out[b * NC + tid] = auxf[tid] + auxf[NC + tid] + fc_b[tid];
}

// ---------------------------------------------------------------------------
extern "C" void kernel_launch(void* const* d_in, const int* in_sizes, int n_in,
                              void* d_out, int out_size) {
    const int*   x       = (const int*)  d_in[0];
    const float* embed_w = (const float*)d_in[1];
    const float* conv_w  = (const float*)d_in[2];
    const float* conv_b  = (const float*)d_in[3];
    const float* fc3_w   = (const float*)d_in[4];
    const float* fc3_b   = (const float*)d_in[5];
    const float* fc4_w   = (const float*)d_in[6];
    const float* fc4_b   = (const float*)d_in[7];
    const float* fc5_w   = (const float*)d_in[8];
    const float* fc5_b   = (const float*)d_in[9];
    const float* fc_w    = (const float*)d_in[10];
    const float* fc_b    = (const float*)d_in[11];
    float* out = (float*)d_out;

    static int smem_set = 0;
    if (!smem_set) {
        cudaFuncSetAttribute(epilogue_kernel,
                             cudaFuncAttributeMaxDynamicSharedMemorySize, EPI_SMEM);
        smem_set = 1;
    }

    gather_kernel<<<NB * CH, 320>>>(x, embed_w, fc3_w, fc4_w, fc5_w);
    epilogue_kernel<<<NB, 256, EPI_SMEM>>>(conv_w, conv_b, fc3_w, fc3_b,
                                           fc4_w, fc4_b, fc5_w, fc5_b,
                                           fc_w, fc_b, out);
}